// round 3
// baseline (speedup 1.0000x reference)
#include <cuda_runtime.h>

// out[i, :] = sum_k ppr_scores[i,k] * x[ppr_idx[i,k], :]
// N=100000, K=32, D=128 (fp32). One warp per output row; lane l holds
// (idx[l], score[l]) broadcast via shfl. Warp reads neighbor rows as
// coalesced 512B loads. x (51MB) is L2-resident.
//
// R3 changes:
//  - back to R1 occupancy shape (32-reg budget, occ ~89%): R2 proved
//    occupancy > per-warp MLP depth at this saturation level.
//  - __ldcg on x: gather stream never L1-hits (random 51MB working set),
//    so skip L1 line allocation/fill work and treat L1tex as a pass-through
//    to L2. Goal: unpin L1 (was 82.5%) and let L2 climb past 83%.
//  - batch of 4 in-flight rows (fits 32-reg budget without spills).

#define KNEIGH 32
#define DVEC   32   // D/4 float4 per row

__global__ __launch_bounds__(256) void ppr_gather_kernel(
    const float4* __restrict__ x,      // [N, 32] float4
    const int*    __restrict__ idx,    // [N, 32]
    const float*  __restrict__ sc,     // [N, 32]
    float4*       __restrict__ out,    // [N, 32] float4
    int n)
{
    const int warp = (blockIdx.x * blockDim.x + threadIdx.x) >> 5;
    const int lane = threadIdx.x & 31;
    if (warp >= n) return;

    const int   my_j = idx[warp * KNEIGH + lane];
    const float my_s = sc[warp * KNEIGH + lane];

    float4 acc0 = make_float4(0.f, 0.f, 0.f, 0.f);
    float4 acc1 = make_float4(0.f, 0.f, 0.f, 0.f);

    #pragma unroll
    for (int k = 0; k < KNEIGH; k += 4) {
        // 4 independent L2-path row loads in flight per warp; latency is
        // covered primarily by ~56 resident warps/SM.
        float4 v[4];
        float  s[4];
        #pragma unroll
        for (int u = 0; u < 4; ++u) {
            const int jk = __shfl_sync(0xffffffffu, my_j, k + u);
            s[u]         = __shfl_sync(0xffffffffu, my_s, k + u);
            v[u]         = __ldcg(&x[(long long)jk * DVEC + lane]);
        }
        acc0.x += s[0] * v[0].x;  acc0.y += s[0] * v[0].y;
        acc0.z += s[0] * v[0].z;  acc0.w += s[0] * v[0].w;
        acc1.x += s[1] * v[1].x;  acc1.y += s[1] * v[1].y;
        acc1.z += s[1] * v[1].z;  acc1.w += s[1] * v[1].w;
        acc0.x += s[2] * v[2].x;  acc0.y += s[2] * v[2].y;
        acc0.z += s[2] * v[2].z;  acc0.w += s[2] * v[2].w;
        acc1.x += s[3] * v[3].x;  acc1.y += s[3] * v[3].y;
        acc1.z += s[3] * v[3].z;  acc1.w += s[3] * v[3].w;
    }

    float4 r;
    r.x = acc0.x + acc1.x;
    r.y = acc0.y + acc1.y;
    r.z = acc0.z + acc1.z;
    r.w = acc0.w + acc1.w;
    out[warp * DVEC + lane] = r;
}

extern "C" void kernel_launch(void* const* d_in, const int* in_sizes, int n_in,
                              void* d_out, int out_size)
{
    const float4* x   = (const float4*)d_in[0];   // [N, D] fp32
    const int*    idx = (const int*)d_in[1];      // [N, K] int32
    const float*  sc  = (const float*)d_in[2];    // [N, K] fp32
    float4*       out = (float4*)d_out;           // [N, D] fp32

    const int n = in_sizes[1] / KNEIGH;           // N rows

    const int warps_per_block = 8;                // 256 threads
    const int blocks = (n + warps_per_block - 1) / warps_per_block;
    ppr_gather_kernel<<<blocks, warps_per_block * 32>>>(x, idx, sc, out, n);
}